// round 15
// baseline (speedup 1.0000x reference)
#include <cuda_runtime.h>
#include <math.h>

#define TT 4096
#define II 512
#define HH 1024
#define OO 256

#define REC_GRID 128
#define REC_THREADS 256   // 8 warps; warp w owns hidden unit blockIdx.x*8+w
#define UNITS_PER_CTA 8

// Scratch (allocation-free: __device__ globals)
__device__ float g_gx[4][TT][HH];        // per-gate input projections
__device__ float g_h[(TT + 1) * HH];     // row 0 = h_{-1} = 0, row t+1 = h_t
__device__ unsigned g_bar;               // grid barrier counter (monotonic per launch)

// ---------------------------------------------------------------------------
__global__ void init_kernel() {
    int i = blockIdx.x * blockDim.x + threadIdx.x;
    if (i < HH) g_h[i] = 0.0f;
    if (i == 0) g_bar = 0u;
}

// ---------------------------------------------------------------------------
// C[M,N] = A[M,K] @ B[N,K]^T + bias[N]   (both A and B are K-contiguous)
// ---------------------------------------------------------------------------
__global__ __launch_bounds__(256) void gemm_tn_bias(
    const float* __restrict__ A, const float* __restrict__ B,
    const float* __restrict__ bias, float* __restrict__ C,
    int M, int N, int K)
{
    __shared__ float As[16][68];
    __shared__ float Bs[16][68];

    const int bm = blockIdx.y * 64;
    const int bn = blockIdx.x * 64;
    const int tid = threadIdx.x;

    const int lr = tid >> 2;
    const int lk = (tid & 3) << 2;
    const int tx = tid & 15;
    const int ty = tid >> 4;

    float acc[4][4] = {};

    for (int k0 = 0; k0 < K; k0 += 16) {
        float4 av = *(const float4*)(A + (size_t)(bm + lr) * K + k0 + lk);
        float4 bv = *(const float4*)(B + (size_t)(bn + lr) * K + k0 + lk);
        __syncthreads();
        As[lk + 0][lr] = av.x; As[lk + 1][lr] = av.y;
        As[lk + 2][lr] = av.z; As[lk + 3][lr] = av.w;
        Bs[lk + 0][lr] = bv.x; Bs[lk + 1][lr] = bv.y;
        Bs[lk + 2][lr] = bv.z; Bs[lk + 3][lr] = bv.w;
        __syncthreads();
#pragma unroll
        for (int kk = 0; kk < 16; kk++) {
            float4 af = *(const float4*)&As[kk][ty * 4];
            float4 bf = *(const float4*)&Bs[kk][tx * 4];
            float am[4] = {af.x, af.y, af.z, af.w};
            float bn_[4] = {bf.x, bf.y, bf.z, bf.w};
#pragma unroll
            for (int i = 0; i < 4; i++)
#pragma unroll
                for (int j = 0; j < 4; j++)
                    acc[i][j] += am[i] * bn_[j];
        }
    }

    const int row = bm + ty * 4;
    const int col = bn + tx * 4;
    float b0 = bias[col + 0], b1 = bias[col + 1], b2 = bias[col + 2], b3 = bias[col + 3];
#pragma unroll
    for (int i = 0; i < 4; i++) {
        float4 out;
        out.x = acc[i][0] + b0;
        out.y = acc[i][1] + b1;
        out.z = acc[i][2] + b2;
        out.w = acc[i][3] + b3;
        *(float4*)&C[(size_t)(row + i) * N + col] = out;
    }
}

__device__ __forceinline__ float fast_sigmoid(float x) {
    return 0.5f * __tanhf(0.5f * x) + 0.5f;   // one MUFU, no divide
}

// ---------------------------------------------------------------------------
// Persistent recurrence. 128 CTAs, 8 warps each; warp w owns unit b*8+w.
// h staged through SMEM (r13). Barrier: release-RED arrival; wait uses a
// ROTATING 4-SLOT relaxed poll — 4 independent counter loads in flight, so
// the sampling period drops from one L2 round trip (~260 cyc) to ~65 cyc.
// ---------------------------------------------------------------------------
__global__ __launch_bounds__(REC_THREADS, 1) void lstm_rec(
    const float* __restrict__ Whf, const float* __restrict__ Whi,
    const float* __restrict__ Whc, const float* __restrict__ Who)
{
    const int w = threadIdx.x >> 5;
    const int l = threadIdx.x & 31;
    const int unit = blockIdx.x * UNITS_PER_CTA + w;

    __shared__ __align__(16) float sh_h[HH];

    // Recurrent weights into registers (once). Lane l chunk i: h[l*4+128*i ..+4)
    float4 wf[8], wi[8], wc[8], wo[8];
    {
        const float* rf = Whf + (size_t)unit * HH;
        const float* ri = Whi + (size_t)unit * HH;
        const float* rc = Whc + (size_t)unit * HH;
        const float* ro = Who + (size_t)unit * HH;
#pragma unroll
        for (int i = 0; i < 8; i++) {
            int c = l * 4 + 128 * i;
            wf[i] = *(const float4*)(rf + c);
            wi[i] = *(const float4*)(ri + c);
            wc[i] = *(const float4*)(rc + c);
            wo[i] = *(const float4*)(ro + c);
        }
    }

    float cst = 0.0f;  // cell state (lane 0)

    // Prefetch gx for t=0
    float gxf = 0.f, gxi = 0.f, gxc = 0.f, gxo = 0.f;
    if (l == 0) {
        gxf = __ldcg(&g_gx[0][0][unit]);
        gxi = __ldcg(&g_gx[1][0][unit]);
        gxc = __ldcg(&g_gx[2][0][unit]);
        gxo = __ldcg(&g_gx[3][0][unit]);
    }

    const int seg = w * 128 + l * 4;   // this thread's 16B of the h row

    for (int t = 0; t < TT; t++) {
        // ---- cooperative fetch: CTA loads row t ONCE into smem ----
        {
            float4 hv = __ldcg((const float4*)(g_h + (size_t)t * HH + seg));
            *(float4*)&sh_h[seg] = hv;
        }
        __syncthreads();

        float af = 0.f, ai = 0.f, ac = 0.f, ao = 0.f;
#pragma unroll
        for (int i = 0; i < 8; i++) {
            float4 hv = *(const float4*)&sh_h[l * 4 + 128 * i];
            af += wf[i].x * hv.x; ai += wi[i].x * hv.x; ac += wc[i].x * hv.x; ao += wo[i].x * hv.x;
            af += wf[i].y * hv.y; ai += wi[i].y * hv.y; ac += wc[i].y * hv.y; ao += wo[i].y * hv.y;
            af += wf[i].z * hv.z; ai += wi[i].z * hv.z; ac += wc[i].z * hv.z; ao += wo[i].z * hv.z;
            af += wf[i].w * hv.w; ai += wi[i].w * hv.w; ac += wc[i].w * hv.w; ao += wo[i].w * hv.w;
        }
#pragma unroll
        for (int off = 16; off > 0; off >>= 1) {
            af += __shfl_xor_sync(0xffffffffu, af, off);
            ai += __shfl_xor_sync(0xffffffffu, ai, off);
            ac += __shfl_xor_sync(0xffffffffu, ac, off);
            ao += __shfl_xor_sync(0xffffffffu, ao, off);
        }

        if (l == 0) {
            float f_ = fast_sigmoid(af + gxf);
            float i_ = fast_sigmoid(ai + gxi);
            float cd = __tanhf(ac + gxc);
            float o_ = fast_sigmoid(ao + gxo);
            cst = f_ * cst + i_ * cd;
            float h_ = o_ * cst;                   // reference omits tanh(c)
            __stcg(&g_h[(size_t)(t + 1) * HH + unit], h_);

            // prefetch gx for next step (overlaps barrier + next dot)
            int tn = (t + 1 < TT) ? (t + 1) : t;
            gxf = __ldcg(&g_gx[0][tn][unit]);
            gxi = __ldcg(&g_gx[1][tn][unit]);
            gxc = __ldcg(&g_gx[2][tn][unit]);
            gxo = __ldcg(&g_gx[3][tn][unit]);
        }

        // ---- grid barrier: release RED + rotating 4-slot relaxed poll ----
        __syncthreads();                           // CTA h stores done
        if (threadIdx.x == 0) {
            asm volatile("red.release.gpu.global.add.u32 [%0], %1;"
                         :: "l"(&g_bar), "r"(1u) : "memory");
            unsigned tgt = (unsigned)(t + 1) * (unsigned)REC_GRID;
            unsigned v0, v1, v2, v3;
            // prime 4 independent in-flight samples
            asm volatile("ld.relaxed.gpu.global.u32 %0, [%1];" : "=r"(v0) : "l"(&g_bar) : "memory");
            asm volatile("ld.relaxed.gpu.global.u32 %0, [%1];" : "=r"(v1) : "l"(&g_bar) : "memory");
            asm volatile("ld.relaxed.gpu.global.u32 %0, [%1];" : "=r"(v2) : "l"(&g_bar) : "memory");
            asm volatile("ld.relaxed.gpu.global.u32 %0, [%1];" : "=r"(v3) : "l"(&g_bar) : "memory");
            for (;;) {
                if (v0 >= tgt) break;
                asm volatile("ld.relaxed.gpu.global.u32 %0, [%1];" : "=r"(v0) : "l"(&g_bar) : "memory");
                if (v1 >= tgt) break;
                asm volatile("ld.relaxed.gpu.global.u32 %0, [%1];" : "=r"(v1) : "l"(&g_bar) : "memory");
                if (v2 >= tgt) break;
                asm volatile("ld.relaxed.gpu.global.u32 %0, [%1];" : "=r"(v2) : "l"(&g_bar) : "memory");
                if (v3 >= tgt) break;
                asm volatile("ld.relaxed.gpu.global.u32 %0, [%1];" : "=r"(v3) : "l"(&g_bar) : "memory");
            }
        }
        __syncthreads();
    }
}

// ---------------------------------------------------------------------------
extern "C" void kernel_launch(void* const* d_in, const int* in_sizes, int n_in,
                              void* d_out, int out_size)
{
    const float* x   = (const float*)d_in[0];
    const float* Wxf = (const float*)d_in[1];
    const float* Whf = (const float*)d_in[2];
    const float* bf  = (const float*)d_in[3];
    const float* Wxi = (const float*)d_in[4];
    const float* Whi = (const float*)d_in[5];
    const float* bi  = (const float*)d_in[6];
    const float* Wxc = (const float*)d_in[7];
    const float* Whc = (const float*)d_in[8];
    const float* bc  = (const float*)d_in[9];
    const float* Wxo = (const float*)d_in[10];
    const float* Who = (const float*)d_in[11];
    const float* bo  = (const float*)d_in[12];
    const float* Wy  = (const float*)d_in[13];
    const float* by  = (const float*)d_in[14];
    float* y = (float*)d_out;

    void* p_gx = nullptr;
    void* p_h  = nullptr;
    cudaGetSymbolAddress(&p_gx, g_gx);
    cudaGetSymbolAddress(&p_h,  g_h);
    float* gx = (float*)p_gx;
    float* hbuf = (float*)p_h;

    init_kernel<<<4, 256>>>();

    // Input projections: 4 GEMMs [4096,1024] = x[4096,512] @ Wx^T + b
    dim3 g1(HH / 64, TT / 64);
    gemm_tn_bias<<<g1, 256>>>(x, Wxf, bf, gx + 0 * (size_t)TT * HH, TT, HH, II);
    gemm_tn_bias<<<g1, 256>>>(x, Wxi, bi, gx + 1 * (size_t)TT * HH, TT, HH, II);
    gemm_tn_bias<<<g1, 256>>>(x, Wxc, bc, gx + 2 * (size_t)TT * HH, TT, HH, II);
    gemm_tn_bias<<<g1, 256>>>(x, Wxo, bo, gx + 3 * (size_t)TT * HH, TT, HH, II);

    // Sequential recurrence (persistent, weights in registers)
    lstm_rec<<<REC_GRID, REC_THREADS>>>(Whf, Whi, Whc, Who);

    // Output projection: y[4096,256] = hs[4096,1024] @ Wy^T + by
    dim3 g2(OO / 64, TT / 64);
    gemm_tn_bias<<<g2, 256>>>(hbuf + HH, Wy, by, y, TT, OO, HH);
}

// round 17
// speedup vs baseline: 1.1007x; 1.1007x over previous
#include <cuda_runtime.h>
#include <math.h>
#include <mma.h>

using namespace nvcuda;

#define TT 4096
#define II 512
#define HH 1024
#define OO 256

#define REC_GRID 128
#define REC_THREADS 256   // 8 warps; warp w owns hidden unit blockIdx.x*8+w
#define UNITS_PER_CTA 8

// Scratch (allocation-free: __device__ globals)
__device__ float g_gx[4][TT][HH];        // per-gate input projections
__device__ float g_h[(TT + 1) * HH];     // row 0 = h_{-1} = 0, row t+1 = h_t
__device__ unsigned g_bar;               // grid barrier counter (monotonic per launch)

// ---------------------------------------------------------------------------
__global__ void init_kernel() {
    int i = blockIdx.x * blockDim.x + threadIdx.x;
    if (i < HH) g_h[i] = 0.0f;
    if (i == 0) g_bar = 0u;
}

// ---------------------------------------------------------------------------
// TF32 tensor-core GEMM: C[M,N] = A[M,K] @ B[N,K]^T   (bias added separately)
// grid: (N/128, M/64), 256 threads = 8 warps as 2(M) x 4(N); warp tile 32x32.
// Accumulators stored DIRECTLY to C with ldm=N (multiple of 4: legal).
// ---------------------------------------------------------------------------
__global__ __launch_bounds__(256) void gemm_tf32(
    const float* __restrict__ A, const float* __restrict__ B,
    float* __restrict__ C, int M, int N, int K)
{
    const int wid  = threadIdx.x >> 5;
    const int warp_m = wid & 1;         // 0..1
    const int warp_n = wid >> 1;        // 0..3
    const int m0 = blockIdx.y * 64 + warp_m * 32;
    const int n0 = blockIdx.x * 128 + warp_n * 32;

    wmma::fragment<wmma::accumulator, 16, 16, 8, float> acc[2][2];
#pragma unroll
    for (int r = 0; r < 2; r++)
#pragma unroll
        for (int c = 0; c < 2; c++)
            wmma::fill_fragment(acc[r][c], 0.0f);

    wmma::fragment<wmma::matrix_a, 16, 16, 8, wmma::precision::tf32, wmma::row_major> af[2];
    wmma::fragment<wmma::matrix_b, 16, 16, 8, wmma::precision::tf32, wmma::col_major> bf[2];

    for (int k = 0; k < K; k += 8) {
#pragma unroll
        for (int r = 0; r < 2; r++) {
            wmma::load_matrix_sync(af[r], A + (size_t)(m0 + 16 * r) * K + k, K);
#pragma unroll
            for (int e = 0; e < af[r].num_elements; e++)
                af[r].x[e] = wmma::__float_to_tf32(af[r].x[e]);
        }
#pragma unroll
        for (int c = 0; c < 2; c++) {
            // B is [N,K] row-major; B^T viewed col-major with ldm=K
            wmma::load_matrix_sync(bf[c], B + (size_t)(n0 + 16 * c) * K + k, K);
#pragma unroll
            for (int e = 0; e < bf[c].num_elements; e++)
                bf[c].x[e] = wmma::__float_to_tf32(bf[c].x[e]);
        }
#pragma unroll
        for (int r = 0; r < 2; r++)
#pragma unroll
            for (int c = 0; c < 2; c++)
                wmma::mma_sync(acc[r][c], af[r], bf[c], acc[r][c]);
    }

#pragma unroll
    for (int r = 0; r < 2; r++)
#pragma unroll
        for (int c = 0; c < 2; c++)
            wmma::store_matrix_sync(C + (size_t)(m0 + 16 * r) * N + (n0 + 16 * c),
                                    acc[r][c], N, wmma::mem_row_major);
}

// ---------------------------------------------------------------------------
// bias add over all 4 gx planes: gx[g][t][u] += bias_g[u]   (float4 strided)
// ---------------------------------------------------------------------------
__global__ void bias_add_kernel(const float* __restrict__ bf,
                                const float* __restrict__ bi,
                                const float* __restrict__ bc,
                                const float* __restrict__ bo)
{
    size_t i4 = (size_t)blockIdx.x * blockDim.x + threadIdx.x;
    size_t n4 = (size_t)4 * TT * HH / 4;
    if (i4 >= n4) return;
    size_t per_gate = (size_t)TT * HH / 4;
    int g = (int)(i4 / per_gate);
    int u4 = (int)((i4 * 4) & (HH - 1));   // HH is power of 2
    const float* bias = (g == 0) ? bf : (g == 1) ? bi : (g == 2) ? bc : bo;
    float4 v = ((float4*)g_gx)[i4];
    v.x += bias[u4 + 0];
    v.y += bias[u4 + 1];
    v.z += bias[u4 + 2];
    v.w += bias[u4 + 3];
    ((float4*)g_gx)[i4] = v;
}

// ---------------------------------------------------------------------------
// fp32 SIMT GEMM (output projection — full precision on y)
// C[M,N] = A[M,K] @ B[N,K]^T + bias[N]
// ---------------------------------------------------------------------------
__global__ __launch_bounds__(256) void gemm_tn_bias(
    const float* __restrict__ A, const float* __restrict__ B,
    const float* __restrict__ bias, float* __restrict__ C,
    int M, int N, int K)
{
    __shared__ float As[16][68];
    __shared__ float Bs[16][68];

    const int bm = blockIdx.y * 64;
    const int bn = blockIdx.x * 64;
    const int tid = threadIdx.x;

    const int lr = tid >> 2;
    const int lk = (tid & 3) << 2;
    const int tx = tid & 15;
    const int ty = tid >> 4;

    float acc[4][4] = {};

    for (int k0 = 0; k0 < K; k0 += 16) {
        float4 av = *(const float4*)(A + (size_t)(bm + lr) * K + k0 + lk);
        float4 bv = *(const float4*)(B + (size_t)(bn + lr) * K + k0 + lk);
        __syncthreads();
        As[lk + 0][lr] = av.x; As[lk + 1][lr] = av.y;
        As[lk + 2][lr] = av.z; As[lk + 3][lr] = av.w;
        Bs[lk + 0][lr] = bv.x; Bs[lk + 1][lr] = bv.y;
        Bs[lk + 2][lr] = bv.z; Bs[lk + 3][lr] = bv.w;
        __syncthreads();
#pragma unroll
        for (int kk = 0; kk < 16; kk++) {
            float4 af = *(const float4*)&As[kk][ty * 4];
            float4 bf = *(const float4*)&Bs[kk][tx * 4];
            float am[4] = {af.x, af.y, af.z, af.w};
            float bn_[4] = {bf.x, bf.y, bf.z, bf.w};
#pragma unroll
            for (int i = 0; i < 4; i++)
#pragma unroll
                for (int j = 0; j < 4; j++)
                    acc[i][j] += am[i] * bn_[j];
        }
    }

    const int row = bm + ty * 4;
    const int col = bn + tx * 4;
    float b0 = bias[col + 0], b1 = bias[col + 1], b2 = bias[col + 2], b3 = bias[col + 3];
#pragma unroll
    for (int i = 0; i < 4; i++) {
        float4 out;
        out.x = acc[i][0] + b0;
        out.y = acc[i][1] + b1;
        out.z = acc[i][2] + b2;
        out.w = acc[i][3] + b3;
        *(float4*)&C[(size_t)(row + i) * N + col] = out;
    }
}

__device__ __forceinline__ float fast_sigmoid(float x) {
    return 0.5f * __tanhf(0.5f * x) + 0.5f;   // one MUFU, no divide
}

// ---------------------------------------------------------------------------
// Persistent recurrence — UNCHANGED from r13 champion.
// ---------------------------------------------------------------------------
__global__ __launch_bounds__(REC_THREADS, 1) void lstm_rec(
    const float* __restrict__ Whf, const float* __restrict__ Whi,
    const float* __restrict__ Whc, const float* __restrict__ Who)
{
    const int w = threadIdx.x >> 5;
    const int l = threadIdx.x & 31;
    const int unit = blockIdx.x * UNITS_PER_CTA + w;

    __shared__ __align__(16) float sh_h[HH];

    // Recurrent weights into registers (once). Lane l chunk i: h[l*4+128*i ..+4)
    float4 wf[8], wi[8], wc[8], wo[8];
    {
        const float* rf = Whf + (size_t)unit * HH;
        const float* ri = Whi + (size_t)unit * HH;
        const float* rc = Whc + (size_t)unit * HH;
        const float* ro = Who + (size_t)unit * HH;
#pragma unroll
        for (int i = 0; i < 8; i++) {
            int c = l * 4 + 128 * i;
            wf[i] = *(const float4*)(rf + c);
            wi[i] = *(const float4*)(ri + c);
            wc[i] = *(const float4*)(rc + c);
            wo[i] = *(const float4*)(ro + c);
        }
    }

    float cst = 0.0f;  // cell state (lane 0)

    // Prefetch gx for t=0
    float gxf = 0.f, gxi = 0.f, gxc = 0.f, gxo = 0.f;
    if (l == 0) {
        gxf = __ldcg(&g_gx[0][0][unit]);
        gxi = __ldcg(&g_gx[1][0][unit]);
        gxc = __ldcg(&g_gx[2][0][unit]);
        gxo = __ldcg(&g_gx[3][0][unit]);
    }

    const int seg = w * 128 + l * 4;   // this thread's 16B of the h row

    for (int t = 0; t < TT; t++) {
        // ---- cooperative fetch: CTA loads row t ONCE into smem ----
        {
            float4 hv = __ldcg((const float4*)(g_h + (size_t)t * HH + seg));
            *(float4*)&sh_h[seg] = hv;
        }
        __syncthreads();

        float af = 0.f, ai = 0.f, ac = 0.f, ao = 0.f;
#pragma unroll
        for (int i = 0; i < 8; i++) {
            float4 hv = *(const float4*)&sh_h[l * 4 + 128 * i];
            af += wf[i].x * hv.x; ai += wi[i].x * hv.x; ac += wc[i].x * hv.x; ao += wo[i].x * hv.x;
            af += wf[i].y * hv.y; ai += wi[i].y * hv.y; ac += wc[i].y * hv.y; ao += wo[i].y * hv.y;
            af += wf[i].z * hv.z; ai += wi[i].z * hv.z; ac += wc[i].z * hv.z; ao += wo[i].z * hv.z;
            af += wf[i].w * hv.w; ai += wi[i].w * hv.w; ac += wc[i].w * hv.w; ao += wo[i].w * hv.w;
        }
#pragma unroll
        for (int off = 16; off > 0; off >>= 1) {
            af += __shfl_xor_sync(0xffffffffu, af, off);
            ai += __shfl_xor_sync(0xffffffffu, ai, off);
            ac += __shfl_xor_sync(0xffffffffu, ac, off);
            ao += __shfl_xor_sync(0xffffffffu, ao, off);
        }

        if (l == 0) {
            float f_ = fast_sigmoid(af + gxf);
            float i_ = fast_sigmoid(ai + gxi);
            float cd = __tanhf(ac + gxc);
            float o_ = fast_sigmoid(ao + gxo);
            cst = f_ * cst + i_ * cd;
            float h_ = o_ * cst;                   // reference omits tanh(c)
            __stcg(&g_h[(size_t)(t + 1) * HH + unit], h_);

            // prefetch gx for next step (overlaps barrier + next dot)
            int tn = (t + 1 < TT) ? (t + 1) : t;
            gxf = __ldcg(&g_gx[0][tn][unit]);
            gxi = __ldcg(&g_gx[1][tn][unit]);
            gxc = __ldcg(&g_gx[2][tn][unit]);
            gxo = __ldcg(&g_gx[3][tn][unit]);
        }

        // ---- grid barrier: release RED + relaxed polls (no confirm trip) ----
        __syncthreads();                           // CTA h stores done
        if (threadIdx.x == 0) {
            asm volatile("red.release.gpu.global.add.u32 [%0], %1;"
                         :: "l"(&g_bar), "r"(1u) : "memory");
            unsigned tgt = (unsigned)(t + 1) * (unsigned)REC_GRID;
            unsigned v;
            do {
                asm volatile("ld.relaxed.gpu.global.u32 %0, [%1];"
                             : "=r"(v) : "l"(&g_bar) : "memory");
            } while (v < tgt);
        }
        __syncthreads();
    }
}

// ---------------------------------------------------------------------------
extern "C" void kernel_launch(void* const* d_in, const int* in_sizes, int n_in,
                              void* d_out, int out_size)
{
    const float* x   = (const float*)d_in[0];
    const float* Wxf = (const float*)d_in[1];
    const float* Whf = (const float*)d_in[2];
    const float* bf  = (const float*)d_in[3];
    const float* Wxi = (const float*)d_in[4];
    const float* Whi = (const float*)d_in[5];
    const float* bi  = (const float*)d_in[6];
    const float* Wxc = (const float*)d_in[7];
    const float* Whc = (const float*)d_in[8];
    const float* bc  = (const float*)d_in[9];
    const float* Wxo = (const float*)d_in[10];
    const float* Who = (const float*)d_in[11];
    const float* bo  = (const float*)d_in[12];
    const float* Wy  = (const float*)d_in[13];
    const float* by  = (const float*)d_in[14];
    float* y = (float*)d_out;

    void* p_gx = nullptr;
    void* p_h  = nullptr;
    cudaGetSymbolAddress(&p_gx, g_gx);
    cudaGetSymbolAddress(&p_h,  g_h);
    float* gx = (float*)p_gx;
    float* hbuf = (float*)p_h;

    init_kernel<<<4, 256>>>();

    // Input projections: 4 TF32 tensor-core GEMMs [4096,1024] = x @ Wx^T
    dim3 gt(HH / 128, TT / 64);   // (8, 64)
    gemm_tf32<<<gt, 256>>>(x, Wxf, gx + 0 * (size_t)TT * HH, TT, HH, II);
    gemm_tf32<<<gt, 256>>>(x, Wxi, gx + 1 * (size_t)TT * HH, TT, HH, II);
    gemm_tf32<<<gt, 256>>>(x, Wxc, gx + 2 * (size_t)TT * HH, TT, HH, II);
    gemm_tf32<<<gt, 256>>>(x, Wxo, gx + 3 * (size_t)TT * HH, TT, HH, II);

    // Fold biases into gx
    {
        size_t n4 = (size_t)4 * TT * HH / 4;
        int blocks = (int)((n4 + 255) / 256);
        bias_add_kernel<<<blocks, 256>>>(bf, bi, bc, bo);
    }

    // Sequential recurrence (persistent, weights in registers)
    lstm_rec<<<REC_GRID, REC_THREADS>>>(Whf, Whi, Whc, Who);

    // Output projection (fp32 for full precision on y)
    dim3 g2(OO / 64, TT / 64);
    gemm_tn_bias<<<g2, 256>>>(hbuf + HH, Wy, by, y, TT, OO, HH);
}